// round 4
// baseline (speedup 1.0000x reference)
#include <cuda_runtime.h>

// GaussianEdgeGuide, 2-kernel formulation, separable box3.
//
// Algebra: softmax over the 9 neighborhood positions of
//   -theta*(edge_center + edge_neighbor - max_edge)
// has edge_center and max_edge constant along the softmax axis, so
//   weight_k(q) = E(q+d_k) / S(q),   E(x) = exp(-theta*edge(x)) (E=1 outside),
//   S(q) = sum_k E(q+d_k).
// One iteration: mask'(q) = box3(mask*E)(q) / S(q)   (mask zero-padded).
// box3 is separable: vertical-3 then horizontal-3. Vertical passes use
// register rolling (thread owns contiguous rows of one column): ~1.4 LDS/px
// instead of 9. Horizontal passes fuse the per-pixel IE / W multiply.
//
// Kernel 1 (prep): per pixel, E = exp(-40*edge), W = 1/box3(E), IE = W*E.
// Kernel 2 (stencil): one CTA per (batch, channel, 32x32 tile).

#define NB   8
#define NC   19
#define HW   256
#define NPIX (HW * HW)
#define TILE 32
#define ES   37                 // smem row stride (odd -> bank spread)
#define MS   35
#define PS   35

__device__ float g_E [NB * NPIX];   // exp(-40*edge)
__device__ float g_W [NB * NPIX];   // 1 / box3(E)
__device__ float g_IE[NB * NPIX];   // W * E

// ---------------------------------------------------------------------------
// Kernel 1: per-pixel E, W, IE.
// ---------------------------------------------------------------------------
__global__ __launch_bounds__(256, 4)
void geg_prep(const float* __restrict__ edge)
{
    __shared__ float sE[34 * PS];   // 34x34 E with halo 1, E=1 outside image

    const int tid = threadIdx.x;
    const int h0 = blockIdx.y * TILE, w0 = blockIdx.x * TILE;
    const int n  = blockIdx.z;
    const float* eimg = edge + (n << 16);

    for (int idx = tid; idx < 34 * 34; idx += 256) {
        int i = idx / 34, j = idx - i * 34;
        int gy = h0 - 1 + i, gx = w0 - 1 + j;
        float e = 1.0f;  // exp(-40 * 0) at zero-padded border
        if ((unsigned)gy < (unsigned)HW && (unsigned)gx < (unsigned)HW)
            e = __expf(-40.0f * eimg[(gy << 8) + gx]);
        sE[i * PS + j] = e;
    }
    __syncthreads();

    const int tj = tid & 31, tb = tid >> 5;
    #pragma unroll
    for (int k = 0; k < 4; ++k) {
        int ti = tb + 8 * k;
        const float* p = &sE[ti * PS + tj];
        float s = p[0]        + p[1]          + p[2]
                + p[PS]       + p[PS + 1]     + p[PS + 2]
                + p[2 * PS]   + p[2 * PS + 1] + p[2 * PS + 2];
        float w  = __fdividef(1.0f, s);
        float ec = p[PS + 1];
        int g = (n << 16) + ((h0 + ti) << 8) + (w0 + tj);
        g_E [g] = ec;
        g_W [g] = w;
        g_IE[g] = w * ec;
    }
}

// ---------------------------------------------------------------------------
// Kernel 2: one (batch, channel, tile) per CTA; separable fused double box3.
//
// Coordinate frames (relative to tile origin h0,w0):
//   sP : rows/cols -2..33  (36x36)  = mask*E, 0 outside image
//   sV : pass-1 vertical sums, rows -1..32 (idx 0..33) x cols -2..33 (0..35)
//        reused for pass-2 vertical sums, rows 0..31 x cols -1..32 (0..33)
//   sM : iter-1 result * IE, rows/cols -1..32 (34x34), 0 outside image
// ---------------------------------------------------------------------------
__global__ __launch_bounds__(256, 4)
void geg_stencil(const float* __restrict__ mask,
                 float* __restrict__ out)
{
    __shared__ float sP[36 * ES];
    __shared__ float sV[36 * ES];
    __shared__ float sM[34 * MS];

    const int tid = threadIdx.x;
    const int tj  = tid & 31, tb = tid >> 5;
    const int h0 = blockIdx.y * TILE, w0 = blockIdx.x * TILE;
    const int z  = blockIdx.z;            // n * NC + c
    const int n  = z / NC;

    const float* mch = mask + ((size_t)z << 16);
    float*       och = out  + ((size_t)z << 16);
    const float* Eb  = g_E  + (n << 16);
    const float* IEb = g_IE + (n << 16);
    const float* Wb  = g_W  + (n << 16);

    // ---- Pass 0: sP = mask * E over the 36x36 halo tile ----
    for (int idx = tid; idx < 36 * 36; idx += 256) {
        int i = idx / 36, j = idx - i * 36;
        int gy = h0 - 2 + i, gx = w0 - 2 + j;
        float m = 0.0f;  // zero-padded mask -> P = 0 outside
        if ((unsigned)gy < (unsigned)HW && (unsigned)gx < (unsigned)HW) {
            int g = (gy << 8) + gx;
            m = mch[g] * Eb[g];
        }
        sP[i * ES + j] = m;
    }
    __syncthreads();

    // ---- Pass 1 (V1): sV[a][x] = sP[a][x]+sP[a+1][x]+sP[a+2][x]
    //      a in 0..33, x in 0..35; warp tb owns contiguous rows, rolling regs.
    {
        const int a0  = tb * 4;
        const int cnt = (tb == 7) ? 6 : 4;      // uniform per warp
        for (int x = tj; x < 36; x += 32) {     // tj, and tj<4 also 32+tj
            const float* p = &sP[a0 * ES + x];
            float*       q = &sV[a0 * ES + x];
            float r0 = p[0], r1 = p[ES];
            p += 2 * ES;
            #pragma unroll 4
            for (int k = 0; k < cnt; ++k) {
                float r2 = *p; p += ES;
                *q = r0 + r1 + r2; q += ES;
                r0 = r1; r1 = r2;
            }
        }
    }
    __syncthreads();

    // ---- Pass 2 (H1): sM[a][b] = (sV[a][b]+sV[a][b+1]+sV[a][b+2]) * IE
    //      a in 0..33, b in 0..33; zero outside image.
    #pragma unroll
    for (int m = 0; m < 5; ++m) {
        int a = tb + 8 * m;
        if (a < 34) {
            for (int b = tj; b < 34; b += 32) {
                const float* v = &sV[a * ES + b];
                float s = v[0] + v[1] + v[2];
                int gy = h0 - 1 + a, gx = w0 - 1 + b;
                float val = 0.0f;
                if ((unsigned)gy < (unsigned)HW && (unsigned)gx < (unsigned)HW)
                    val = s * IEb[(gy << 8) + gx];
                sM[a * MS + b] = val;
            }
        }
    }
    __syncthreads();

    // ---- Pass 3 (V2): sV[k][b] = sM[k][b]+sM[k+1][b]+sM[k+2][b]
    //      k in 0..31, b in 0..33; rolling regs again (sV reuse is safe:
    //      its pass-1 contents were fully consumed in pass 2).
    {
        const int k0 = tb * 4;
        for (int b = tj; b < 34; b += 32) {
            const float* p = &sM[k0 * MS + b];
            float*       q = &sV[k0 * ES + b];
            float r0 = p[0], r1 = p[MS];
            p += 2 * MS;
            #pragma unroll
            for (int k = 0; k < 4; ++k) {
                float r2 = *p; p += MS;
                *q = r0 + r1 + r2; q += ES;
                r0 = r1; r1 = r2;
            }
        }
    }
    __syncthreads();

    // ---- Pass 4 (H2): out[k][j] = (sV[k][j]+sV[k][j+1]+sV[k][j+2]) * W ----
    #pragma unroll
    for (int m = 0; m < 4; ++m) {
        int k = tb + 8 * m;
        const float* v = &sV[k * ES + tj];
        float s = v[0] + v[1] + v[2];
        int g = ((h0 + k) << 8) + (w0 + tj);
        och[g] = s * Wb[g];
    }
}

extern "C" void kernel_launch(void* const* d_in, const int* in_sizes, int n_in,
                              void* d_out, int out_size)
{
    const float* mask = (const float*)d_in[0];
    const float* edge = (const float*)d_in[1];
    // d_in[2] = iter_n is fixed at 2 by the problem setup; 2 iterations fused.
    (void)in_sizes; (void)n_in; (void)out_size;

    dim3 gp(HW / TILE, HW / TILE, NB);        // 8 x 8 x 8
    geg_prep<<<gp, 256>>>(edge);

    dim3 gs(HW / TILE, HW / TILE, NB * NC);   // 8 x 8 x 152 = 9728 CTAs
    geg_stencil<<<gs, 256>>>(mask, (float*)d_out);
}

// round 6
// speedup vs baseline: 1.3864x; 1.3864x over previous
#include <cuda_runtime.h>

// GaussianEdgeGuide, 2-kernel formulation, float4-vectorized direct 9-pt.
//
// Algebra: softmax over the 9 neighborhood positions of
//   -theta*(edge_center + edge_neighbor - max_edge)
// has edge_center and max_edge constant along the softmax axis, so
//   weight_k(q) = E(q+d_k) / S(q),   E(x) = exp(-theta*edge(x)) (E=1 outside),
//   S(q) = sum_k E(q+d_k).
// One iteration: mask'(q) = box3(mask*E)(q) / S(q)   (mask zero-padded).
//
// Kernel 1 (prep): per pixel, E = exp(-40*edge), W = 1/box3(E), IE = W*E.
// Kernel 2 (stencil): one CTA per (batch, channel, 32x32 tile), 2 barriers,
// every item handles 4 consecutive pixels (LDG.128/LDS.128/STS.128/STG.128,
// in-thread separable 3x3 = 20 FADD / 4 px). Width-4 groups are entirely
// in- or out-of-bounds in x (widths are multiples of 4), so one predicate
// per item suffices.

#define NB   8
#define NC   19
#define HW   256
#define NPIX (HW * HW)
#define TILE 32
#define RS   40                 // smem row stride in floats (16B-aligned rows)

__device__ __align__(16) float g_E [NB * NPIX];   // exp(-40*edge)
__device__ __align__(16) float g_W [NB * NPIX];   // 1 / box3(E)
__device__ __align__(16) float g_IE[NB * NPIX];   // W * E

// ---------------------------------------------------------------------------
// Kernel 1: per-pixel E, W, IE.
// ---------------------------------------------------------------------------
__global__ __launch_bounds__(256, 4)
void geg_prep(const float* __restrict__ edge)
{
    __shared__ float sE[34 * 35];   // 34x34 E with halo 1, E=1 outside image

    const int tid = threadIdx.x;
    const int h0 = blockIdx.y * TILE, w0 = blockIdx.x * TILE;
    const int n  = blockIdx.z;
    const float* eimg = edge + (n << 16);

    for (int idx = tid; idx < 34 * 34; idx += 256) {
        int i = idx / 34, j = idx - i * 34;
        int gy = h0 - 1 + i, gx = w0 - 1 + j;
        float e = 1.0f;  // exp(-40 * 0) at zero-padded border
        if ((unsigned)gy < (unsigned)HW && (unsigned)gx < (unsigned)HW)
            e = __expf(-40.0f * eimg[(gy << 8) + gx]);
        sE[i * 35 + j] = e;
    }
    __syncthreads();

    const int tj = tid & 31, tb = tid >> 5;
    #pragma unroll
    for (int k = 0; k < 4; ++k) {
        int ti = tb + 8 * k;
        const float* p = &sE[ti * 35 + tj];
        float s = p[0]      + p[1]      + p[2]
                + p[35]     + p[36]     + p[37]
                + p[70]     + p[71]     + p[72];
        float w  = __fdividef(1.0f, s);
        float ec = p[36];
        int g = (n << 16) + ((h0 + ti) << 8) + (w0 + tj);
        g_E [g] = ec;
        g_W [g] = w;
        g_IE[g] = w * ec;
    }
}

// ---------------------------------------------------------------------------
// Kernel 2: one (batch, channel, tile) per CTA.
//
// smem frames: pixel col j maps to row-offset j+8 (consistently for writer
// and reader; the j=32..35 group's offsets 40..43 physically land in the
// next row's first floats — a consistent alias, covered by the +8 tail).
//   sPr : 36 rows (gy = h0-2 .. h0+33), pixel cols j = -4..35 = mask*E (0 OOB)
//   sMr : 34 rows (a  = -1  .. 32),     pixel cols j = -4..35 = box3(P)*IE
// Garbage cells (offset 3 reads, j=-4 results) are provably never read by
// pass 2 (it touches offsets 7..40 = pixels -1..32 only).
// ---------------------------------------------------------------------------
__global__ __launch_bounds__(256)
void geg_stencil(const float* __restrict__ mask,
                 float* __restrict__ out)
{
    __shared__ __align__(16) float sPr[36 * RS + 8];
    __shared__ __align__(16) float sMr[34 * RS + 8];

    const int tid = threadIdx.x;
    const int h0 = blockIdx.y * TILE, w0 = blockIdx.x * TILE;
    const int z  = blockIdx.z;            // n * NC + c
    const int n  = z / NC;

    const float4* mch = (const float4*)(mask + ((size_t)z << 16));
    float4*       och = (float4*)(out  + ((size_t)z << 16));
    const float4* Eb  = (const float4*)(g_E  + (n << 16));
    const float4* IEb = (const float4*)(g_IE + (n << 16));
    const float4* Wb  = (const float4*)(g_W  + (n << 16));
    // float4 index of pixel (gy, gx) with gx % 4 == 0:  (gy<<6) + (gx>>2)

    // ---- Pass 0: sP = mask * E, 36 rows x 10 groups of 4 ----
    for (int idx = tid; idx < 360; idx += 256) {
        int i = idx / 10, g = idx - i * 10;   // i: 0..35, g: 0..9
        int gy = h0 + i - 2;
        int gx = w0 + 4 * g - 4;              // group j0 = 4g - 4
        float4 p = make_float4(0.f, 0.f, 0.f, 0.f);
        if ((unsigned)gy < (unsigned)HW && (unsigned)gx < (unsigned)HW) {
            int q = (gy << 6) + (gx >> 2);
            float4 m = mch[q], e = Eb[q];
            p = make_float4(m.x * e.x, m.y * e.y, m.z * e.z, m.w * e.w);
        }
        *(float4*)&sPr[4 + i * RS + 4 * g] = p;
    }
    __syncthreads();

    // ---- Pass 1: sM = box3(sP) * IE, 34 rows x 10 groups ----
    for (int idx = tid; idx < 340; idx += 256) {
        int ai = idx / 10, g = idx - ai * 10; // ai: 0..33 (a = ai-1), g: 0..9
        int base = 4 + ai * RS + 4 * g;       // rows r = ai, ai+1, ai+2
        float4 v0 = *(const float4*)&sPr[base];
        float4 v1 = *(const float4*)&sPr[base + RS];
        float4 v2 = *(const float4*)&sPr[base + 2 * RS];
        float l = sPr[base - 1]     + sPr[base + RS - 1] + sPr[base + 2 * RS - 1];
        float r = sPr[base + 4]     + sPr[base + RS + 4] + sPr[base + 2 * RS + 4];
        float c1 = v0.x + v1.x + v2.x;
        float c2 = v0.y + v1.y + v2.y;
        float c3 = v0.z + v1.z + v2.z;
        float c4 = v0.w + v1.w + v2.w;
        int gy = h0 + ai - 1;
        int gx = w0 + 4 * g - 4;
        float4 res = make_float4(0.f, 0.f, 0.f, 0.f);
        if ((unsigned)gy < (unsigned)HW && (unsigned)gx < (unsigned)HW) {
            float4 ie = IEb[(gy << 6) + (gx >> 2)];
            res.x = (l  + c1 + c2) * ie.x;
            res.y = (c1 + c2 + c3) * ie.y;
            res.z = (c2 + c3 + c4) * ie.z;
            res.w = (c3 + c4 + r ) * ie.w;
        }
        *(float4*)&sMr[4 + ai * RS + 4 * g] = res;
    }
    __syncthreads();

    // ---- Pass 2: out = box3(sM) * W, exactly one item per thread ----
    {
        int k = tid >> 3, g = tid & 7;        // k: 0..31, group j0 = 4g
        int base = 4 + k * RS + 4 * g + 4;    // sM rows k, k+1, k+2
        float4 v0 = *(const float4*)&sMr[base];
        float4 v1 = *(const float4*)&sMr[base + RS];
        float4 v2 = *(const float4*)&sMr[base + 2 * RS];
        float l = sMr[base - 1]     + sMr[base + RS - 1] + sMr[base + 2 * RS - 1];
        float r = sMr[base + 4]     + sMr[base + RS + 4] + sMr[base + 2 * RS + 4];
        float c1 = v0.x + v1.x + v2.x;
        float c2 = v0.y + v1.y + v2.y;
        float c3 = v0.z + v1.z + v2.z;
        float c4 = v0.w + v1.w + v2.w;
        int gy = h0 + k, gx = w0 + 4 * g;
        int q = (gy << 6) + (gx >> 2);
        float4 w = Wb[q];
        float4 o;
        o.x = (l  + c1 + c2) * w.x;
        o.y = (c1 + c2 + c3) * w.y;
        o.z = (c2 + c3 + c4) * w.z;
        o.w = (c3 + c4 + r ) * w.w;
        och[q] = o;
    }
}

extern "C" void kernel_launch(void* const* d_in, const int* in_sizes, int n_in,
                              void* d_out, int out_size)
{
    const float* mask = (const float*)d_in[0];
    const float* edge = (const float*)d_in[1];
    // d_in[2] = iter_n is fixed at 2 by the problem setup; 2 iterations fused.
    (void)in_sizes; (void)n_in; (void)out_size;

    dim3 gp(HW / TILE, HW / TILE, NB);        // 8 x 8 x 8
    geg_prep<<<gp, 256>>>(edge);

    dim3 gs(HW / TILE, HW / TILE, NB * NC);   // 8 x 8 x 152 = 9728 CTAs
    geg_stencil<<<gs, 256>>>(mask, (float*)d_out);
}

// round 8
// speedup vs baseline: 1.6764x; 1.2092x over previous
#include <cuda_runtime.h>

// GaussianEdgeGuide — prep kernel + smem-free register-rolling stencil.
//
// Algebra: softmax over the 9 neighborhood positions of
//   -theta*(edge_center + edge_neighbor - max_edge)
// has edge_center and max_edge constant along the softmax axis, so
//   weight_k(q) = E(q+d_k) / S(q),   E(x) = exp(-theta*edge(x)) (E=1 outside),
//   S(q) = sum_k E(q+d_k).
// One iteration: mask'(q) = box3(mask*E)(q) / S(q)   (mask zero-padded).
// iter1 = box3(mask*E) * IE  (IE = W*E),  out = box3(iter1) * W.
//
// Stencil: tile 128x64 per CTA, 8 warps, warp owns 8 output rows. Lane l owns
// the 4-px group x = w0+4l; lanes 0/31 additionally carry the tile's x-halo
// group (w0-4 / w0+128) in registers. Vertical 3-sums roll in registers over
// 12 streamed input rows; horizontal 3-sums use 2 warp shuffles per row.
// No shared memory in the stencil at all (R6 was l1tex-bound at 85%, mostly
// LDS/STS wavefronts).
//
// R7 bug fixed: the prologue load of P row R0-1 was unguarded; for warp 0 of
// the top tile row gy = -1 -> illegal access. Now zero-filled when OOB.

#define NB   8
#define NC   19
#define HW   256
#define NPIX (HW * HW)

__device__ __align__(16) float g_E [NB * NPIX];   // exp(-40*edge)
__device__ __align__(16) float g_W [NB * NPIX];   // 1 / box3(E)
__device__ __align__(16) float g_IE[NB * NPIX];   // W * E

// ---------------------------------------------------------------------------
// Kernel 1: per-pixel E, W, IE (32x32 tiles; unchanged from R6).
// ---------------------------------------------------------------------------
__global__ __launch_bounds__(256, 4)
void geg_prep(const float* __restrict__ edge)
{
    __shared__ float sE[34 * 35];   // 34x34 E with halo 1, E=1 outside image

    const int tid = threadIdx.x;
    const int h0 = blockIdx.y * 32, w0 = blockIdx.x * 32;
    const int n  = blockIdx.z;
    const float* eimg = edge + (n << 16);

    for (int idx = tid; idx < 34 * 34; idx += 256) {
        int i = idx / 34, j = idx - i * 34;
        int gy = h0 - 1 + i, gx = w0 - 1 + j;
        float e = 1.0f;  // exp(-40 * 0) at zero-padded border
        if ((unsigned)gy < 256u && (unsigned)gx < 256u)
            e = __expf(-40.0f * eimg[(gy << 8) + gx]);
        sE[i * 35 + j] = e;
    }
    __syncthreads();

    const int tj = tid & 31, tb = tid >> 5;
    #pragma unroll
    for (int k = 0; k < 4; ++k) {
        int ti = tb + 8 * k;
        const float* p = &sE[ti * 35 + tj];
        float s = p[0]  + p[1]  + p[2]
                + p[35] + p[36] + p[37]
                + p[70] + p[71] + p[72];
        float w  = __fdividef(1.0f, s);
        float ec = p[36];
        int g = (n << 16) + ((h0 + ti) << 8) + (w0 + tj);
        g_E [g] = ec;
        g_W [g] = w;
        g_IE[g] = w * ec;
    }
}

// ---------------------------------------------------------------------------
// Kernel 2: smem-free stencil. Grid (2, 4, NB*NC), block 256.
// ---------------------------------------------------------------------------
__global__ __launch_bounds__(256, 2)
void geg_stencil(const float* __restrict__ mask,
                 float* __restrict__ out)
{
    const unsigned FULL = 0xffffffffu;
    const int lane = threadIdx.x & 31;
    const int warp = threadIdx.x >> 5;
    const int w0 = blockIdx.x << 7;        // 0 or 128
    const int h0 = blockIdx.y << 6;        // 0, 64, 128, 192
    const int z  = blockIdx.z;             // n * NC + c
    const int n  = z / NC;

    const float4* mch = (const float4*)(mask + ((size_t)z << 16));
    float4*       och = (float4*)(out  + ((size_t)z << 16));
    const float4* Eb  = (const float4*)(g_E  + (n << 16));
    const float4* IEb = (const float4*)(g_IE + (n << 16));
    const float4* Wb  = (const float4*)(g_W  + (n << 16));
    const float*  IEs = g_IE + (n << 16);  // scalar view for halo IE

    const int  qm     = (w0 >> 2) + lane;                         // main f4 col
    const bool haloOK = (lane == 0) ? (w0 > 0)
                      : (lane == 31) ? (w0 + 128 < HW) : false;
    const int  qh     = (lane == 0) ? (w0 >> 2) - 1 : (w0 >> 2) + 32;
    const int  hx     = (lane == 0) ? (w0 - 1)      : (w0 + 128); // halo px x

    const int R0 = h0 + (warp << 3);       // first output row of this warp

    // --- rolling state ---
    float4 p0, p1, p2;                     // main P = mask*E rows
    float4 q0, q1, q2;                     // halo  P rows (lanes 0/31)
    float4 m0, m1, m2;                     // iter1 rows (main)
    float  g0, g1, g2;                     // iter1 halo scalar rows

    // prologue: P rows R0-2, R0-1 (both zero when above the image)
    {
        int gy = R0 - 2;
        if ((unsigned)gy < 256u) {
            float4 m = mch[(gy << 6) + qm], e = Eb[(gy << 6) + qm];
            p0 = make_float4(m.x*e.x, m.y*e.y, m.z*e.z, m.w*e.w);
        } else p0 = make_float4(0.f, 0.f, 0.f, 0.f);
        if (haloOK && (unsigned)gy < 256u) {
            float4 m = mch[(gy << 6) + qh], e = Eb[(gy << 6) + qh];
            q0 = make_float4(m.x*e.x, m.y*e.y, m.z*e.z, m.w*e.w);
        } else q0 = make_float4(0.f, 0.f, 0.f, 0.f);
        gy = R0 - 1;                       // -1 for warp 0 of the top tiles!
        if ((unsigned)gy < 256u) {
            float4 m = mch[(gy << 6) + qm], e = Eb[(gy << 6) + qm];
            p1 = make_float4(m.x*e.x, m.y*e.y, m.z*e.z, m.w*e.w);
        } else p1 = make_float4(0.f, 0.f, 0.f, 0.f);
        if (haloOK && (unsigned)gy < 256u) {
            float4 m = mch[(gy << 6) + qh], e = Eb[(gy << 6) + qh];
            q1 = make_float4(m.x*e.x, m.y*e.y, m.z*e.z, m.w*e.w);
        } else q1 = make_float4(0.f, 0.f, 0.f, 0.f);
    }
    // silence "maybe uninitialized"; never read before set (first output at
    // a = R0+1 reads m0 written at a = R0-1).
    m1 = m2 = make_float4(0.f, 0.f, 0.f, 0.f);
    g1 = g2 = 0.f;

    #pragma unroll
    for (int a = R0 - 1; a <= R0 + 8; ++a) {   // iter1 row a
        // load P row a+1
        int gy = a + 1;
        if ((unsigned)gy < 256u) {
            float4 m = mch[(gy << 6) + qm], e = Eb[(gy << 6) + qm];
            p2 = make_float4(m.x*e.x, m.y*e.y, m.z*e.z, m.w*e.w);
        } else p2 = make_float4(0.f, 0.f, 0.f, 0.f);
        if (haloOK && (unsigned)gy < 256u) {
            float4 m = mch[(gy << 6) + qh], e = Eb[(gy << 6) + qh];
            q2 = make_float4(m.x*e.x, m.y*e.y, m.z*e.z, m.w*e.w);
        } else q2 = make_float4(0.f, 0.f, 0.f, 0.f);

        // vertical 3-sums at row a
        float c1 = p0.x + p1.x + p2.x;
        float c2 = p0.y + p1.y + p2.y;
        float c3 = p0.z + p1.z + p2.z;
        float c4 = p0.w + p1.w + p2.w;
        float h1 = q0.x + q1.x + q2.x;
        float h2 = q0.y + q1.y + q2.y;
        float h3 = q0.z + q1.z + q2.z;
        float h4 = q0.w + q1.w + q2.w;

        // horizontal neighbor exchange (unconditional, warp-uniform)
        float cl = __shfl_up_sync  (FULL, c4, 1);  // left lane's last col
        float cr = __shfl_down_sync(FULL, c1, 1);  // right lane's first col
        if (lane == 0)  cl = h4;   // halo col w0-1 (0 at image edge)
        if (lane == 31) cr = h1;   // halo col w0+128

        // iter1 row a (zero outside image)
        float4 mrow;
        float  ghal = 0.f;
        if ((unsigned)a < 256u) {
            float4 ie = IEb[(a << 6) + qm];
            mrow.x = (cl + c1 + c2) * ie.x;
            mrow.y = (c1 + c2 + c3) * ie.y;
            mrow.z = (c2 + c3 + c4) * ie.z;
            mrow.w = (c3 + c4 + cr) * ie.w;
            if (haloOK) {
                float ieh = IEs[(a << 8) + hx];
                float s = (lane == 0) ? (h3 + h4 + c1)   // cols hx-1,hx,hx+1
                                      : (c4 + h1 + h2);
                ghal = s * ieh;
            }
        } else {
            mrow = make_float4(0.f, 0.f, 0.f, 0.f);
        }

        // roll
        p0 = p1; p1 = p2;
        q0 = q1; q1 = q2;
        m0 = m1; m1 = m2; m2 = mrow;
        g0 = g1; g1 = g2; g2 = ghal;

        if (a >= R0 + 1) {
            int r = a - 1;                    // output row, in [0,255]
            float v1 = m0.x + m1.x + m2.x;
            float v2 = m0.y + m1.y + m2.y;
            float v3 = m0.z + m1.z + m2.z;
            float v4 = m0.w + m1.w + m2.w;
            float vh = g0 + g1 + g2;

            float vl = __shfl_up_sync  (FULL, v4, 1);
            float vr = __shfl_down_sync(FULL, v1, 1);
            if (lane == 0)  vl = vh;          // 0 when tile is at left edge
            if (lane == 31) vr = vh;

            float4 w = Wb[(r << 6) + qm];
            float4 o;
            o.x = (vl + v1 + v2) * w.x;
            o.y = (v1 + v2 + v3) * w.y;
            o.z = (v2 + v3 + v4) * w.z;
            o.w = (v3 + v4 + vr) * w.w;
            och[(r << 6) + qm] = o;
        }
    }
}

extern "C" void kernel_launch(void* const* d_in, const int* in_sizes, int n_in,
                              void* d_out, int out_size)
{
    const float* mask = (const float*)d_in[0];
    const float* edge = (const float*)d_in[1];
    // d_in[2] = iter_n is fixed at 2 by the problem setup; 2 iterations fused.
    (void)in_sizes; (void)n_in; (void)out_size;

    dim3 gp(HW / 32, HW / 32, NB);            // 8 x 8 x 8
    geg_prep<<<gp, 256>>>(edge);

    dim3 gs(HW / 128, HW / 64, NB * NC);      // 2 x 4 x 152 = 1216 CTAs
    geg_stencil<<<gs, 256>>>(mask, (float*)d_out);
}

// round 9
// speedup vs baseline: 2.1101x; 1.2587x over previous
#include <cuda_runtime.h>

// GaussianEdgeGuide — prep kernel + smem-free register-rolling stencil.
//
// Algebra: softmax over the 9 neighborhood positions of
//   -theta*(edge_center + edge_neighbor - max_edge)
// has edge_center and max_edge constant along the softmax axis, so
//   weight_k(q) = E(q+d_k) / S(q),   E(x) = exp(-theta*edge(x)) (E=1 outside),
//   S(q) = sum_k E(q+d_k).
// One iteration: mask'(q) = box3(mask*E)(q) / S(q)   (mask zero-padded).
// iter1 = box3(mask*E) * IE  (IE = W*E),  out = box3(iter1) * W.
//
// Stencil: tile 128x32 per CTA, 4 warps, warp owns 8 output rows. Lane l owns
// the 4-px group x = w0+4l; lanes 0/31 additionally carry the tile's x-halo
// group in registers. Vertical 3-sums roll in registers; horizontal 3-sums
// use 2 warp shuffles per row. No shared memory.
//
// R8 ncu: occ 23.5% (94 regs, 2x256-thr CTAs/SM), issue 21.7%, nothing
// saturated -> DRAM-latency bound. This round: 128-thr CTAs +
// __launch_bounds__(128,6) -> 24 warps/SM (37.5% occ), +50% concurrency.

#define NB   8
#define NC   19
#define HW   256
#define NPIX (HW * HW)

__device__ __align__(16) float g_E [NB * NPIX];   // exp(-40*edge)
__device__ __align__(16) float g_W [NB * NPIX];   // 1 / box3(E)
__device__ __align__(16) float g_IE[NB * NPIX];   // W * E

// ---------------------------------------------------------------------------
// Kernel 1: per-pixel E, W, IE (32x32 tiles; unchanged).
// ---------------------------------------------------------------------------
__global__ __launch_bounds__(256, 4)
void geg_prep(const float* __restrict__ edge)
{
    __shared__ float sE[34 * 35];   // 34x34 E with halo 1, E=1 outside image

    const int tid = threadIdx.x;
    const int h0 = blockIdx.y * 32, w0 = blockIdx.x * 32;
    const int n  = blockIdx.z;
    const float* eimg = edge + (n << 16);

    for (int idx = tid; idx < 34 * 34; idx += 256) {
        int i = idx / 34, j = idx - i * 34;
        int gy = h0 - 1 + i, gx = w0 - 1 + j;
        float e = 1.0f;  // exp(-40 * 0) at zero-padded border
        if ((unsigned)gy < 256u && (unsigned)gx < 256u)
            e = __expf(-40.0f * eimg[(gy << 8) + gx]);
        sE[i * 35 + j] = e;
    }
    __syncthreads();

    const int tj = tid & 31, tb = tid >> 5;
    #pragma unroll
    for (int k = 0; k < 4; ++k) {
        int ti = tb + 8 * k;
        const float* p = &sE[ti * 35 + tj];
        float s = p[0]  + p[1]  + p[2]
                + p[35] + p[36] + p[37]
                + p[70] + p[71] + p[72];
        float w  = __fdividef(1.0f, s);
        float ec = p[36];
        int g = (n << 16) + ((h0 + ti) << 8) + (w0 + tj);
        g_E [g] = ec;
        g_W [g] = w;
        g_IE[g] = w * ec;
    }
}

// ---------------------------------------------------------------------------
// Kernel 2: smem-free stencil. Grid (2, 8, NB*NC), block 128 (4 warps).
// ---------------------------------------------------------------------------
__global__ __launch_bounds__(128, 6)
void geg_stencil(const float* __restrict__ mask,
                 float* __restrict__ out)
{
    const unsigned FULL = 0xffffffffu;
    const int lane = threadIdx.x & 31;
    const int warp = threadIdx.x >> 5;     // 0..3
    const int w0 = blockIdx.x << 7;        // 0 or 128
    const int h0 = blockIdx.y << 5;        // 0, 32, ..., 224
    const int z  = blockIdx.z;             // n * NC + c
    const int n  = z / NC;

    const float4* mch = (const float4*)(mask + ((size_t)z << 16));
    float4*       och = (float4*)(out  + ((size_t)z << 16));
    const float4* Eb  = (const float4*)(g_E  + (n << 16));
    const float4* IEb = (const float4*)(g_IE + (n << 16));
    const float4* Wb  = (const float4*)(g_W  + (n << 16));
    const float*  IEs = g_IE + (n << 16);  // scalar view for halo IE

    const int  qm     = (w0 >> 2) + lane;                         // main f4 col
    const bool haloOK = (lane == 0) ? (w0 > 0)
                      : (lane == 31) ? (w0 + 128 < HW) : false;
    const int  qh     = (lane == 0) ? (w0 >> 2) - 1 : (w0 >> 2) + 32;
    const int  hx     = (lane == 0) ? (w0 - 1)      : (w0 + 128); // halo px x

    const int R0 = h0 + (warp << 3);       // first output row of this warp

    // --- rolling state ---
    float4 p0, p1, p2;                     // main P = mask*E rows
    float4 q0, q1, q2;                     // halo  P rows (lanes 0/31)
    float4 m0, m1, m2;                     // iter1 rows (main)
    float  g0, g1, g2;                     // iter1 halo scalar rows

    // prologue: P rows R0-2, R0-1 (both zero when above the image)
    {
        int gy = R0 - 2;
        if ((unsigned)gy < 256u) {
            float4 m = mch[(gy << 6) + qm], e = Eb[(gy << 6) + qm];
            p0 = make_float4(m.x*e.x, m.y*e.y, m.z*e.z, m.w*e.w);
        } else p0 = make_float4(0.f, 0.f, 0.f, 0.f);
        if (haloOK && (unsigned)gy < 256u) {
            float4 m = mch[(gy << 6) + qh], e = Eb[(gy << 6) + qh];
            q0 = make_float4(m.x*e.x, m.y*e.y, m.z*e.z, m.w*e.w);
        } else q0 = make_float4(0.f, 0.f, 0.f, 0.f);
        gy = R0 - 1;                       // -1 for warp 0 of the top tiles
        if ((unsigned)gy < 256u) {
            float4 m = mch[(gy << 6) + qm], e = Eb[(gy << 6) + qm];
            p1 = make_float4(m.x*e.x, m.y*e.y, m.z*e.z, m.w*e.w);
        } else p1 = make_float4(0.f, 0.f, 0.f, 0.f);
        if (haloOK && (unsigned)gy < 256u) {
            float4 m = mch[(gy << 6) + qh], e = Eb[(gy << 6) + qh];
            q1 = make_float4(m.x*e.x, m.y*e.y, m.z*e.z, m.w*e.w);
        } else q1 = make_float4(0.f, 0.f, 0.f, 0.f);
    }
    // silence "maybe uninitialized"; never read before set (first output at
    // a = R0+1 reads m0 written at a = R0-1).
    m1 = m2 = make_float4(0.f, 0.f, 0.f, 0.f);
    g1 = g2 = 0.f;

    #pragma unroll
    for (int a = R0 - 1; a <= R0 + 8; ++a) {   // iter1 row a
        // load P row a+1
        int gy = a + 1;
        if ((unsigned)gy < 256u) {
            float4 m = mch[(gy << 6) + qm], e = Eb[(gy << 6) + qm];
            p2 = make_float4(m.x*e.x, m.y*e.y, m.z*e.z, m.w*e.w);
        } else p2 = make_float4(0.f, 0.f, 0.f, 0.f);
        if (haloOK && (unsigned)gy < 256u) {
            float4 m = mch[(gy << 6) + qh], e = Eb[(gy << 6) + qh];
            q2 = make_float4(m.x*e.x, m.y*e.y, m.z*e.z, m.w*e.w);
        } else q2 = make_float4(0.f, 0.f, 0.f, 0.f);

        // vertical 3-sums at row a
        float c1 = p0.x + p1.x + p2.x;
        float c2 = p0.y + p1.y + p2.y;
        float c3 = p0.z + p1.z + p2.z;
        float c4 = p0.w + p1.w + p2.w;
        float h1 = q0.x + q1.x + q2.x;
        float h2 = q0.y + q1.y + q2.y;
        float h3 = q0.z + q1.z + q2.z;
        float h4 = q0.w + q1.w + q2.w;

        // horizontal neighbor exchange (unconditional, warp-uniform)
        float cl = __shfl_up_sync  (FULL, c4, 1);  // left lane's last col
        float cr = __shfl_down_sync(FULL, c1, 1);  // right lane's first col
        if (lane == 0)  cl = h4;   // halo col w0-1 (0 at image edge)
        if (lane == 31) cr = h1;   // halo col w0+128

        // iter1 row a (zero outside image)
        float4 mrow;
        float  ghal = 0.f;
        if ((unsigned)a < 256u) {
            float4 ie = IEb[(a << 6) + qm];
            mrow.x = (cl + c1 + c2) * ie.x;
            mrow.y = (c1 + c2 + c3) * ie.y;
            mrow.z = (c2 + c3 + c4) * ie.z;
            mrow.w = (c3 + c4 + cr) * ie.w;
            if (haloOK) {
                float ieh = IEs[(a << 8) + hx];
                float s = (lane == 0) ? (h3 + h4 + c1)   // cols hx-1,hx,hx+1
                                      : (c4 + h1 + h2);
                ghal = s * ieh;
            }
        } else {
            mrow = make_float4(0.f, 0.f, 0.f, 0.f);
        }

        // roll
        p0 = p1; p1 = p2;
        q0 = q1; q1 = q2;
        m0 = m1; m1 = m2; m2 = mrow;
        g0 = g1; g1 = g2; g2 = ghal;

        if (a >= R0 + 1) {
            int r = a - 1;                    // output row, in [0,255]
            float v1 = m0.x + m1.x + m2.x;
            float v2 = m0.y + m1.y + m2.y;
            float v3 = m0.z + m1.z + m2.z;
            float v4 = m0.w + m1.w + m2.w;
            float vh = g0 + g1 + g2;

            float vl = __shfl_up_sync  (FULL, v4, 1);
            float vr = __shfl_down_sync(FULL, v1, 1);
            if (lane == 0)  vl = vh;          // 0 when tile is at left edge
            if (lane == 31) vr = vh;

            float4 w = Wb[(r << 6) + qm];
            float4 o;
            o.x = (vl + v1 + v2) * w.x;
            o.y = (v1 + v2 + v3) * w.y;
            o.z = (v2 + v3 + v4) * w.z;
            o.w = (v3 + v4 + vr) * w.w;
            och[(r << 6) + qm] = o;
        }
    }
}

extern "C" void kernel_launch(void* const* d_in, const int* in_sizes, int n_in,
                              void* d_out, int out_size)
{
    const float* mask = (const float*)d_in[0];
    const float* edge = (const float*)d_in[1];
    // d_in[2] = iter_n is fixed at 2 by the problem setup; 2 iterations fused.
    (void)in_sizes; (void)n_in; (void)out_size;

    dim3 gp(HW / 32, HW / 32, NB);            // 8 x 8 x 8
    geg_prep<<<gp, 256>>>(edge);

    dim3 gs(HW / 128, HW / 32, NB * NC);      // 2 x 8 x 152 = 2432 CTAs
    geg_stencil<<<gs, 128>>>(mask, (float*)d_out);
}

// round 10
// speedup vs baseline: 2.2439x; 1.0634x over previous
#include <cuda_runtime.h>

// GaussianEdgeGuide — prep kernel + smem-free register-rolling stencil.
//
// Algebra: softmax over the 9 neighborhood positions of
//   -theta*(edge_center + edge_neighbor - max_edge)
// has edge_center and max_edge constant along the softmax axis, so
//   weight_k(q) = E(q+d_k) / S(q),   E(x) = exp(-theta*edge(x)) (E=1 outside),
//   S(q) = sum_k E(q+d_k).
// One iteration: mask'(q) = box3(mask*E)(q) / S(q)   (mask zero-padded).
// iter1 = box3(mask*E) * IE  (IE = W*E),  out = box3(iter1) * W.
//
// Stencil: tile 128x32 per CTA, 4 warps, warp owns 8 output rows. Lane l owns
// the 4-px group x = w0+4l; lanes 0/31 carry ONLY the 2 halo columns they
// actually consume (float2). Vertical 3-sums roll in registers; horizontal
// 3-sums use 2 warp shuffles per row. No shared memory.
//
// R9 ncu: occ 32.3%, issue 29.2%, nothing saturated; throughput has scaled
// ~linearly with resident warps for two rounds. This round: float2 halo
// (-6 regs of state) + __launch_bounds__(128,8) -> 64-reg cap -> 32 warps/SM.

#define NB   8
#define NC   19
#define HW   256
#define NPIX (HW * HW)

__device__ __align__(16) float g_E [NB * NPIX];   // exp(-40*edge)
__device__ __align__(16) float g_W [NB * NPIX];   // 1 / box3(E)
__device__ __align__(16) float g_IE[NB * NPIX];   // W * E

// ---------------------------------------------------------------------------
// Kernel 1: per-pixel E, W, IE (32x32 tiles; unchanged).
// ---------------------------------------------------------------------------
__global__ __launch_bounds__(256, 4)
void geg_prep(const float* __restrict__ edge)
{
    __shared__ float sE[34 * 35];   // 34x34 E with halo 1, E=1 outside image

    const int tid = threadIdx.x;
    const int h0 = blockIdx.y * 32, w0 = blockIdx.x * 32;
    const int n  = blockIdx.z;
    const float* eimg = edge + (n << 16);

    for (int idx = tid; idx < 34 * 34; idx += 256) {
        int i = idx / 34, j = idx - i * 34;
        int gy = h0 - 1 + i, gx = w0 - 1 + j;
        float e = 1.0f;  // exp(-40 * 0) at zero-padded border
        if ((unsigned)gy < 256u && (unsigned)gx < 256u)
            e = __expf(-40.0f * eimg[(gy << 8) + gx]);
        sE[i * 35 + j] = e;
    }
    __syncthreads();

    const int tj = tid & 31, tb = tid >> 5;
    #pragma unroll
    for (int k = 0; k < 4; ++k) {
        int ti = tb + 8 * k;
        const float* p = &sE[ti * 35 + tj];
        float s = p[0]  + p[1]  + p[2]
                + p[35] + p[36] + p[37]
                + p[70] + p[71] + p[72];
        float w  = __fdividef(1.0f, s);
        float ec = p[36];
        int g = (n << 16) + ((h0 + ti) << 8) + (w0 + tj);
        g_E [g] = ec;
        g_W [g] = w;
        g_IE[g] = w * ec;
    }
}

// ---------------------------------------------------------------------------
// Kernel 2: smem-free stencil. Grid (2, 8, NB*NC), block 128 (4 warps).
// ---------------------------------------------------------------------------
__global__ __launch_bounds__(128, 8)
void geg_stencil(const float* __restrict__ mask,
                 float* __restrict__ out)
{
    const unsigned FULL = 0xffffffffu;
    const int lane = threadIdx.x & 31;
    const int warp = threadIdx.x >> 5;     // 0..3
    const int w0 = blockIdx.x << 7;        // 0 or 128
    const int h0 = blockIdx.y << 5;        // 0, 32, ..., 224
    const int z  = blockIdx.z;             // n * NC + c
    const int n  = z / NC;

    const float4* mch = (const float4*)(mask + ((size_t)z << 16));
    float4*       och = (float4*)(out  + ((size_t)z << 16));
    const float4* Eb  = (const float4*)(g_E  + (n << 16));
    const float4* IEb = (const float4*)(g_IE + (n << 16));
    const float4* Wb  = (const float4*)(g_W  + (n << 16));
    const float*  mfs = mask + ((size_t)z << 16);   // scalar views for halo
    const float*  Efs = g_E  + (n << 16);
    const float*  IEs = g_IE + (n << 16);

    const int  qm     = (w0 >> 2) + lane;                         // main f4 col
    const bool haloOK = (lane == 0) ? (w0 > 0)
                      : (lane == 31) ? (w0 + 128 < HW) : false;
    // 2 halo columns per side: lane 0 -> w0-2, w0-1; lane 31 -> w0+128, w0+129
    const int  hb     = (lane == 0) ? (w0 - 2) : (w0 + 128);      // 8B-aligned
    const int  hx     = (lane == 0) ? (w0 - 1) : (w0 + 128);      // halo out px

    const int R0 = h0 + (warp << 3);       // first output row of this warp

    // --- rolling state ---
    float4 p0, p1, p2;                     // main P = mask*E rows
    float2 q0, q1, q2;                     // halo  P rows (2 cols, lanes 0/31)
    float4 m0, m1, m2;                     // iter1 rows (main)
    float  g0, g1, g2;                     // iter1 halo scalar rows

    // prologue: P rows R0-2, R0-1 (zero when above the image)
    {
        int gy = R0 - 2;
        if ((unsigned)gy < 256u) {
            float4 m = mch[(gy << 6) + qm], e = Eb[(gy << 6) + qm];
            p0 = make_float4(m.x*e.x, m.y*e.y, m.z*e.z, m.w*e.w);
        } else p0 = make_float4(0.f, 0.f, 0.f, 0.f);
        if (haloOK && (unsigned)gy < 256u) {
            float2 m = *(const float2*)(mfs + (gy << 8) + hb);
            float2 e = *(const float2*)(Efs + (gy << 8) + hb);
            q0 = make_float2(m.x*e.x, m.y*e.y);
        } else q0 = make_float2(0.f, 0.f);
        gy = R0 - 1;                       // -1 for warp 0 of the top tiles
        if ((unsigned)gy < 256u) {
            float4 m = mch[(gy << 6) + qm], e = Eb[(gy << 6) + qm];
            p1 = make_float4(m.x*e.x, m.y*e.y, m.z*e.z, m.w*e.w);
        } else p1 = make_float4(0.f, 0.f, 0.f, 0.f);
        if (haloOK && (unsigned)gy < 256u) {
            float2 m = *(const float2*)(mfs + (gy << 8) + hb);
            float2 e = *(const float2*)(Efs + (gy << 8) + hb);
            q1 = make_float2(m.x*e.x, m.y*e.y);
        } else q1 = make_float2(0.f, 0.f);
    }
    // silence "maybe uninitialized"; never read before set (first output at
    // a = R0+1 reads m0 written at a = R0-1).
    m1 = m2 = make_float4(0.f, 0.f, 0.f, 0.f);
    g1 = g2 = 0.f;

    #pragma unroll
    for (int a = R0 - 1; a <= R0 + 8; ++a) {   // iter1 row a
        // load P row a+1
        int gy = a + 1;
        if ((unsigned)gy < 256u) {
            float4 m = mch[(gy << 6) + qm], e = Eb[(gy << 6) + qm];
            p2 = make_float4(m.x*e.x, m.y*e.y, m.z*e.z, m.w*e.w);
        } else p2 = make_float4(0.f, 0.f, 0.f, 0.f);
        if (haloOK && (unsigned)gy < 256u) {
            float2 m = *(const float2*)(mfs + (gy << 8) + hb);
            float2 e = *(const float2*)(Efs + (gy << 8) + hb);
            q2 = make_float2(m.x*e.x, m.y*e.y);
        } else q2 = make_float2(0.f, 0.f);

        // vertical 3-sums at row a
        float c1 = p0.x + p1.x + p2.x;
        float c2 = p0.y + p1.y + p2.y;
        float c3 = p0.z + p1.z + p2.z;
        float c4 = p0.w + p1.w + p2.w;
        float hA = q0.x + q1.x + q2.x;     // lane0: col w0-2 | lane31: w0+128
        float hB = q0.y + q1.y + q2.y;     // lane0: col w0-1 | lane31: w0+129

        // horizontal neighbor exchange (unconditional, warp-uniform)
        float cl = __shfl_up_sync  (FULL, c4, 1);  // left lane's last col
        float cr = __shfl_down_sync(FULL, c1, 1);  // right lane's first col
        if (lane == 0)  cl = hB;   // col w0-1 (0 at image edge)
        if (lane == 31) cr = hA;   // col w0+128

        // iter1 row a (zero outside image)
        float4 mrow;
        float  ghal = 0.f;
        if ((unsigned)a < 256u) {
            float4 ie = IEb[(a << 6) + qm];
            mrow.x = (cl + c1 + c2) * ie.x;
            mrow.y = (c1 + c2 + c3) * ie.y;
            mrow.z = (c2 + c3 + c4) * ie.z;
            mrow.w = (c3 + c4 + cr) * ie.w;
            if (haloOK) {
                float ieh = IEs[(a << 8) + hx];
                float s = (lane == 0) ? (hA + hB + c1)   // cols w0-2,w0-1,w0
                                      : (c4 + hA + hB);  // w0+127,+128,+129
                ghal = s * ieh;
            }
        } else {
            mrow = make_float4(0.f, 0.f, 0.f, 0.f);
        }

        // roll
        p0 = p1; p1 = p2;
        q0 = q1; q1 = q2;
        m0 = m1; m1 = m2; m2 = mrow;
        g0 = g1; g1 = g2; g2 = ghal;

        if (a >= R0 + 1) {
            int r = a - 1;                    // output row, in [0,255]
            float v1 = m0.x + m1.x + m2.x;
            float v2 = m0.y + m1.y + m2.y;
            float v3 = m0.z + m1.z + m2.z;
            float v4 = m0.w + m1.w + m2.w;
            float vh = g0 + g1 + g2;

            float vl = __shfl_up_sync  (FULL, v4, 1);
            float vr = __shfl_down_sync(FULL, v1, 1);
            if (lane == 0)  vl = vh;          // 0 when tile is at left edge
            if (lane == 31) vr = vh;

            float4 w = Wb[(r << 6) + qm];
            float4 o;
            o.x = (vl + v1 + v2) * w.x;
            o.y = (v1 + v2 + v3) * w.y;
            o.z = (v2 + v3 + v4) * w.z;
            o.w = (v3 + v4 + vr) * w.w;
            och[(r << 6) + qm] = o;
        }
    }
}

extern "C" void kernel_launch(void* const* d_in, const int* in_sizes, int n_in,
                              void* d_out, int out_size)
{
    const float* mask = (const float*)d_in[0];
    const float* edge = (const float*)d_in[1];
    // d_in[2] = iter_n is fixed at 2 by the problem setup; 2 iterations fused.
    (void)in_sizes; (void)n_in; (void)out_size;

    dim3 gp(HW / 32, HW / 32, NB);            // 8 x 8 x 8
    geg_prep<<<gp, 256>>>(edge);

    dim3 gs(HW / 128, HW / 32, NB * NC);      // 2 x 8 x 152 = 2432 CTAs
    geg_stencil<<<gs, 128>>>(mask, (float*)d_out);
}

// round 11
// speedup vs baseline: 2.2571x; 1.0059x over previous
#include <cuda_runtime.h>

// GaussianEdgeGuide — prep kernel + smem-free, halo-free full-width stencil.
//
// Algebra: softmax over the 9 neighborhood positions of
//   -theta*(edge_center + edge_neighbor - max_edge)
// has edge_center and max_edge constant along the softmax axis, so
//   weight_k(q) = E(q+d_k) / S(q),   E(x) = exp(-theta*edge(x)) (E=1 outside),
//   S(q) = sum_k E(q+d_k).
// One iteration: mask'(q) = box3(mask*E)(q) / S(q)   (mask zero-padded).
// iter1 = box3(mask*E) * IE  (IE = W*E),  out = box3(iter1) * W.
//
// Stencil: each warp spans the full 256-px row: lane l owns 4-px groups at
// x=4l (g0) and x=128+4l (g1) -> perfectly contiguous LDG.128s, and the only
// horizontal boundary is the true image border (zero shuffle-in) plus the
// 127<->128 seam (two warp broadcasts). No halo loads/state/predicates at
// all (R10 post-mortem: occupancy scaling saturated; per-warp overhead and
// the halo-laden dependency chain now bind). Vertical 3-sums roll in
// registers; the two groups give 2x ILP on the sum->shuffle->mul chain.

#define NB   8
#define NC   19
#define HW   256
#define NPIX (HW * HW)

__device__ __align__(16) float g_E [NB * NPIX];   // exp(-40*edge)
__device__ __align__(16) float g_W [NB * NPIX];   // 1 / box3(E)
__device__ __align__(16) float g_IE[NB * NPIX];   // W * E

// ---------------------------------------------------------------------------
// Kernel 1: per-pixel E, W, IE (32x32 tiles; unchanged).
// ---------------------------------------------------------------------------
__global__ __launch_bounds__(256, 4)
void geg_prep(const float* __restrict__ edge)
{
    __shared__ float sE[34 * 35];   // 34x34 E with halo 1, E=1 outside image

    const int tid = threadIdx.x;
    const int h0 = blockIdx.y * 32, w0 = blockIdx.x * 32;
    const int n  = blockIdx.z;
    const float* eimg = edge + (n << 16);

    for (int idx = tid; idx < 34 * 34; idx += 256) {
        int i = idx / 34, j = idx - i * 34;
        int gy = h0 - 1 + i, gx = w0 - 1 + j;
        float e = 1.0f;  // exp(-40 * 0) at zero-padded border
        if ((unsigned)gy < 256u && (unsigned)gx < 256u)
            e = __expf(-40.0f * eimg[(gy << 8) + gx]);
        sE[i * 35 + j] = e;
    }
    __syncthreads();

    const int tj = tid & 31, tb = tid >> 5;
    #pragma unroll
    for (int k = 0; k < 4; ++k) {
        int ti = tb + 8 * k;
        const float* p = &sE[ti * 35 + tj];
        float s = p[0]  + p[1]  + p[2]
                + p[35] + p[36] + p[37]
                + p[70] + p[71] + p[72];
        float w  = __fdividef(1.0f, s);
        float ec = p[36];
        int g = (n << 16) + ((h0 + ti) << 8) + (w0 + tj);
        g_E [g] = ec;
        g_W [g] = w;
        g_IE[g] = w * ec;
    }
}

// ---------------------------------------------------------------------------
// Kernel 2: halo-free stencil. Grid (16, NB*NC), block 64 (2 warps).
// Warp owns 8 output rows of the full 256-px width.
// ---------------------------------------------------------------------------
__global__ __launch_bounds__(64, 12)
void geg_stencil(const float* __restrict__ mask,
                 float* __restrict__ out)
{
    const unsigned FULL = 0xffffffffu;
    const int lane = threadIdx.x & 31;
    const int warp = threadIdx.x >> 5;     // 0..1
    const int z    = blockIdx.y;           // n * NC + c
    const int n    = z / NC;

    const float4* mch = (const float4*)(mask + ((size_t)z << 16));
    float4*       och = (float4*)(out  + ((size_t)z << 16));
    const float4* Eb  = (const float4*)(g_E  + (n << 16));
    const float4* IEb = (const float4*)(g_IE + (n << 16));
    const float4* Wb  = (const float4*)(g_W  + (n << 16));

    const int qa = lane;        // f4 col of g0 (px 4*lane)        + row*64
    const int qb = 32 + lane;   // f4 col of g1 (px 128 + 4*lane)  + row*64

    const int R0 = (blockIdx.x << 4) + (warp << 3);  // first output row

    // --- rolling state: P rows (mask*E) and iter1 rows, 2 groups each ---
    float4 a0, a1, a2;   // g0 P rows
    float4 b0, b1, b2;   // g1 P rows
    float4 m0, m1, m2;   // g0 iter1 rows
    float4 u0, u1, u2;   // g1 iter1 rows

    // prologue: P rows R0-2, R0-1 (zero when above the image)
    {
        int gy = R0 - 2;
        if ((unsigned)gy < 256u) {
            float4 m = mch[(gy << 6) + qa], e = Eb[(gy << 6) + qa];
            a0 = make_float4(m.x*e.x, m.y*e.y, m.z*e.z, m.w*e.w);
            m = mch[(gy << 6) + qb]; e = Eb[(gy << 6) + qb];
            b0 = make_float4(m.x*e.x, m.y*e.y, m.z*e.z, m.w*e.w);
        } else {
            a0 = make_float4(0.f, 0.f, 0.f, 0.f);
            b0 = make_float4(0.f, 0.f, 0.f, 0.f);
        }
        gy = R0 - 1;
        if ((unsigned)gy < 256u) {
            float4 m = mch[(gy << 6) + qa], e = Eb[(gy << 6) + qa];
            a1 = make_float4(m.x*e.x, m.y*e.y, m.z*e.z, m.w*e.w);
            m = mch[(gy << 6) + qb]; e = Eb[(gy << 6) + qb];
            b1 = make_float4(m.x*e.x, m.y*e.y, m.z*e.z, m.w*e.w);
        } else {
            a1 = make_float4(0.f, 0.f, 0.f, 0.f);
            b1 = make_float4(0.f, 0.f, 0.f, 0.f);
        }
    }
    // never read before written (first output at a=R0+1 reads m0 from a=R0-1)
    m1 = m2 = u1 = u2 = make_float4(0.f, 0.f, 0.f, 0.f);

    #pragma unroll
    for (int a = R0 - 1; a <= R0 + 8; ++a) {   // iter1 row a
        // load P row a+1
        int gy = a + 1;
        if ((unsigned)gy < 256u) {
            float4 m = mch[(gy << 6) + qa], e = Eb[(gy << 6) + qa];
            a2 = make_float4(m.x*e.x, m.y*e.y, m.z*e.z, m.w*e.w);
            m = mch[(gy << 6) + qb]; e = Eb[(gy << 6) + qb];
            b2 = make_float4(m.x*e.x, m.y*e.y, m.z*e.z, m.w*e.w);
        } else {
            a2 = make_float4(0.f, 0.f, 0.f, 0.f);
            b2 = make_float4(0.f, 0.f, 0.f, 0.f);
        }

        // vertical 3-sums at row a, both groups (independent chains)
        float c1 = a0.x + a1.x + a2.x;
        float c2 = a0.y + a1.y + a2.y;
        float c3 = a0.z + a1.z + a2.z;
        float c4 = a0.w + a1.w + a2.w;
        float d1 = b0.x + b1.x + b2.x;
        float d2 = b0.y + b1.y + b2.y;
        float d3 = b0.z + b1.z + b2.z;
        float d4 = b0.w + b1.w + b2.w;

        // horizontal exchange: neighbors + the 127<->128 seam broadcasts
        float l0 = __shfl_up_sync  (FULL, c4, 1);
        float r0 = __shfl_down_sync(FULL, c1, 1);
        float l1 = __shfl_up_sync  (FULL, d4, 1);
        float r1 = __shfl_down_sync(FULL, d1, 1);
        float s0 = __shfl_sync(FULL, c4, 31);  // px 127 sum
        float s1 = __shfl_sync(FULL, d1, 0);   // px 128 sum
        if (lane == 0)  { l0 = 0.f; l1 = s0; } // px -1 -> zero-pad
        if (lane == 31) { r0 = s1; r1 = 0.f; } // px 256 -> zero-pad

        // iter1 row a (zero outside image)
        float4 mrow, urow;
        if ((unsigned)a < 256u) {
            float4 ie = IEb[(a << 6) + qa];
            mrow.x = (l0 + c1 + c2) * ie.x;
            mrow.y = (c1 + c2 + c3) * ie.y;
            mrow.z = (c2 + c3 + c4) * ie.z;
            mrow.w = (c3 + c4 + r0) * ie.w;
            ie = IEb[(a << 6) + qb];
            urow.x = (l1 + d1 + d2) * ie.x;
            urow.y = (d1 + d2 + d3) * ie.y;
            urow.z = (d2 + d3 + d4) * ie.z;
            urow.w = (d3 + d4 + r1) * ie.w;
        } else {
            mrow = make_float4(0.f, 0.f, 0.f, 0.f);
            urow = make_float4(0.f, 0.f, 0.f, 0.f);
        }

        // roll
        a0 = a1; a1 = a2;
        b0 = b1; b1 = b2;
        m0 = m1; m1 = m2; m2 = mrow;
        u0 = u1; u1 = u2; u2 = urow;

        if (a >= R0 + 1) {
            int r = a - 1;                    // output row, in [0,255]
            float v1 = m0.x + m1.x + m2.x;
            float v2 = m0.y + m1.y + m2.y;
            float v3 = m0.z + m1.z + m2.z;
            float v4 = m0.w + m1.w + m2.w;
            float w1 = u0.x + u1.x + u2.x;
            float w2 = u0.y + u1.y + u2.y;
            float w3 = u0.z + u1.z + u2.z;
            float w4 = u0.w + u1.w + u2.w;

            float L0 = __shfl_up_sync  (FULL, v4, 1);
            float Rr0 = __shfl_down_sync(FULL, v1, 1);
            float L1 = __shfl_up_sync  (FULL, w4, 1);
            float Rr1 = __shfl_down_sync(FULL, w1, 1);
            float S0 = __shfl_sync(FULL, v4, 31);
            float S1 = __shfl_sync(FULL, w1, 0);
            if (lane == 0)  { L0 = 0.f; L1 = S0; }
            if (lane == 31) { Rr0 = S1; Rr1 = 0.f; }

            float4 wgt = Wb[(r << 6) + qa];
            float4 o;
            o.x = (L0 + v1 + v2) * wgt.x;
            o.y = (v1 + v2 + v3) * wgt.y;
            o.z = (v2 + v3 + v4) * wgt.z;
            o.w = (v3 + v4 + Rr0) * wgt.w;
            och[(r << 6) + qa] = o;

            wgt = Wb[(r << 6) + qb];
            o.x = (L1 + w1 + w2) * wgt.x;
            o.y = (w1 + w2 + w3) * wgt.y;
            o.z = (w2 + w3 + w4) * wgt.z;
            o.w = (w3 + w4 + Rr1) * wgt.w;
            och[(r << 6) + qb] = o;
        }
    }
}

extern "C" void kernel_launch(void* const* d_in, const int* in_sizes, int n_in,
                              void* d_out, int out_size)
{
    const float* mask = (const float*)d_in[0];
    const float* edge = (const float*)d_in[1];
    // d_in[2] = iter_n is fixed at 2 by the problem setup; 2 iterations fused.
    (void)in_sizes; (void)n_in; (void)out_size;

    dim3 gp(HW / 32, HW / 32, NB);            // 8 x 8 x 8
    geg_prep<<<gp, 256>>>(edge);

    dim3 gs(HW / 16, NB * NC);                // 16 x 152 = 2432 CTAs
    geg_stencil<<<gs, 64>>>(mask, (float*)d_out);
}